// round 8
// baseline (speedup 1.0000x reference)
#include <cuda_runtime.h>

// Output (1,64,64,64,32) fp32 = 2,097,152 float4.
// K=2 independent chains per thread, chain stride S = 1,048,576 float4
// (= 131072 positions = 32 z-groups): r and c identical across the 2 chains
// (shared row/col index loads + shared partial address), only z differs
// (z0, z0+32). Every STG.128 is warp-dense: consecutive lanes write
// consecutive float4 -> full 128B-line coverage per store instruction.
//
// R2-R7 established a hard ~2.9-3.0 TB/s output-write floor (L2 write path,
// ~1/4 of the LTS read cap) reached identically by per-thread STG and the
// async bulk engine; this round locks the best shape with 512-thread blocks
// and plain stores.
//
// position p = f4_index >> 3 ; c = p & 63, r = (p>>6) & 63, z = p >> 12
// src scalar = in[ ((z_idx[z]*128 + row_idx[r])*128 + col_idx[c]) * 32 ]

#define S_F4    1048576u   // 2097152 / 2
#define TPB     512

__global__ __launch_bounds__(TPB) void sds3d_kernel(
    const float* __restrict__ in,
    const int* __restrict__ z_idx,
    const int* __restrict__ row_idx,
    const int* __restrict__ col_idx,
    float4* __restrict__ out)
{
    unsigned tid = blockIdx.x * (unsigned)TPB + threadIdx.x;  // 0 .. S_F4-1
    unsigned p   = tid >> 3;                          // position 0..131071 (z0 in 0..31)
    unsigned c   = p & 63u;
    unsigned r   = (p >> 6) & 63u;
    unsigned z0  = p >> 12;                           // 0..31

    int ri = __ldg(&row_idx[r]);
    int ci = __ldg(&col_idx[c]);
    unsigned rc = (unsigned)ri * 128u + (unsigned)ci; // shared partial address

    int zi0 = __ldg(&z_idx[z0]);
    int zi1 = __ldg(&z_idx[z0 + 32u]);

    float v0 = __ldg(&in[((unsigned)zi0 * 16384u + rc) * 32u]);
    float v1 = __ldg(&in[((unsigned)zi1 * 16384u + rc) * 32u]);

    float4 o0 = make_float4(v0, v0, v0, v0);
    float4 o1 = make_float4(v1, v1, v1, v1);
    out[tid]        = o0;
    out[tid + S_F4] = o1;
}

extern "C" void kernel_launch(void* const* d_in, const int* in_sizes, int n_in,
                              void* d_out, int out_size)
{
    const float* in      = (const float*)d_in[0];
    const int*   z_idx   = (const int*)d_in[1];
    const int*   row_idx = (const int*)d_in[2];
    const int*   col_idx = (const int*)d_in[3];
    float4* out = (float4*)d_out;

    // S_F4 threads / 512 = 2048 blocks
    sds3d_kernel<<<S_F4 / TPB, TPB>>>(in, z_idx, row_idx, col_idx, out);
}

// round 9
// speedup vs baseline: 1.0836x; 1.0836x over previous
#include <cuda_runtime.h>

// FINAL: Output (1,64,64,64,32) fp32 = 2,097,152 float4.
// K=2 independent chains per thread, chain stride S = 1,048,576 float4
// (= 131072 positions = 32 z-groups): r and c identical across the 2 chains
// (shared row/col index loads + shared partial address), only z differs
// (z0, z0+32). Every STG.128 is warp-dense: consecutive lanes write
// consecutive float4 -> full 128B-line coverage per store instruction.
//
// R2-R8 sweep (ILP 1/2/4/8, 128/256/512 threads, per-thread STG vs async
// bulk-copy engine, plain vs streaming stores) established a hard
// ~2.9-3.0 TB/s output-write floor (L2/DRAM write path) with all SM-side
// pipes <=38%: the mandatory 33.5 MB output stream IS the roofline.
// This is the measured-best configuration (10.976 us).
//
// position p = f4_index >> 3 ; c = p & 63, r = (p>>6) & 63, z = p >> 12
// src scalar = in[ ((z_idx[z]*128 + row_idx[r])*128 + col_idx[c]) * 32 ]

#define S_F4 1048576u   // 2097152 / 2

__global__ __launch_bounds__(256) void sds3d_kernel(
    const float* __restrict__ in,
    const int* __restrict__ z_idx,
    const int* __restrict__ row_idx,
    const int* __restrict__ col_idx,
    float4* __restrict__ out)
{
    unsigned tid = blockIdx.x * 256u + threadIdx.x;   // 0 .. S_F4-1
    unsigned p   = tid >> 3;                          // position 0..131071 (z0 in 0..31)
    unsigned c   = p & 63u;
    unsigned r   = (p >> 6) & 63u;
    unsigned z0  = p >> 12;                           // 0..31

    int ri = __ldg(&row_idx[r]);
    int ci = __ldg(&col_idx[c]);
    unsigned rc = (unsigned)ri * 128u + (unsigned)ci; // shared partial address

    int zi0 = __ldg(&z_idx[z0]);
    int zi1 = __ldg(&z_idx[z0 + 32u]);

    float v0 = __ldg(&in[((unsigned)zi0 * 16384u + rc) * 32u]);
    float v1 = __ldg(&in[((unsigned)zi1 * 16384u + rc) * 32u]);

    __stcs(&out[tid],        make_float4(v0, v0, v0, v0));
    __stcs(&out[tid + S_F4], make_float4(v1, v1, v1, v1));
}

extern "C" void kernel_launch(void* const* d_in, const int* in_sizes, int n_in,
                              void* d_out, int out_size)
{
    const float* in      = (const float*)d_in[0];
    const int*   z_idx   = (const int*)d_in[1];
    const int*   row_idx = (const int*)d_in[2];
    const int*   col_idx = (const int*)d_in[3];
    float4* out = (float4*)d_out;

    // S_F4 threads / 256 = 4096 blocks
    sds3d_kernel<<<4096, 256>>>(in, z_idx, row_idx, col_idx, out);
}

// round 10
// speedup vs baseline: 1.0868x; 1.0030x over previous
#include <cuda_runtime.h>

// Output (1,64,64,64,32) fp32 = 2,097,152 float4 = 1,048,576 aligned 32B chunks.
// One thread per 32B chunk, stored with a single st.global.cs.v8.f32 (sm_100+
// 256-bit store): lane l of a warp writes bytes [32*(base+l), +32) -> one
// fully dense 1KB warp store per instruction. Chunk c covers f4 {2t, 2t+1},
// both inside one gathered-position octet (p = t >> 2), so ONE gathered
// scalar + ONE index triple serves the whole chunk: store instructions,
// gather LDGs and index LDGs are all HALF of the best K=2 kernel.
//
//   c = p & 63, r = (p>>6) & 63, z = p >> 12
//   src = in[ ((z_idx[z]*128 + row_idx[r])*128 + col_idx[c]) * 32 ]

__global__ __launch_bounds__(256) void sds3d_kernel(
    const float* __restrict__ in,
    const int* __restrict__ z_idx,
    const int* __restrict__ row_idx,
    const int* __restrict__ col_idx,
    float* __restrict__ out)
{
    unsigned t = blockIdx.x * 256u + threadIdx.x;   // 0 .. 1,048,575
    unsigned p = t >> 2;                            // gathered position 0..262143
    unsigned c = p & 63u;
    unsigned r = (p >> 6) & 63u;
    unsigned z = p >> 12;

    int zi = __ldg(&z_idx[z]);
    int ri = __ldg(&row_idx[r]);
    int ci = __ldg(&col_idx[c]);

    unsigned src = (((unsigned)zi * 128u + (unsigned)ri) * 128u + (unsigned)ci) * 32u;
    float v = __ldg(&in[src]);

    float* dst = out + (size_t)t * 8u;              // 32B-aligned
    asm volatile(
        "st.global.cs.v8.f32 [%0], {%1, %2, %3, %4, %5, %6, %7, %8};"
        :: "l"(dst), "f"(v), "f"(v), "f"(v), "f"(v),
                     "f"(v), "f"(v), "f"(v), "f"(v)
        : "memory");
}

extern "C" void kernel_launch(void* const* d_in, const int* in_sizes, int n_in,
                              void* d_out, int out_size)
{
    const float* in      = (const float*)d_in[0];
    const int*   z_idx   = (const int*)d_in[1];
    const int*   row_idx = (const int*)d_in[2];
    const int*   col_idx = (const int*)d_in[3];
    float* out = (float*)d_out;

    // 1,048,576 threads / 256 = 4096 blocks
    sds3d_kernel<<<4096, 256>>>(in, z_idx, row_idx, col_idx, out);
}